// round 1
// baseline (speedup 1.0000x reference)
#include <cuda_runtime.h>
#include <cstdint>

#define B_   4
#define T_   4096
#define C_   256
#define NTOK (B_ * T_)   // 16384

// ---------------- scratch (static device arrays; no allocation) --------------
__device__ float g_gn[NTOK * C_];
__device__ float g_q [NTOK * C_];
__device__ float g_k [NTOK * C_];
__device__ float g_v [NTOK * C_];
__device__ float g_s [(size_t)B_ * T_ * T_];   // 268 MB attention scores/probs

// =============================== LayerNorm ==================================
__global__ void __launch_bounds__(256) ln_kernel(const float* __restrict__ x,
                                                 const float* __restrict__ gamma,
                                                 const float* __restrict__ beta,
                                                 float* __restrict__ out) {
    int t = blockIdx.x;
    int c = threadIdx.x;
    size_t idx = (size_t)t * C_ + c;
    float v = x[idx];
    float s = v, sq = v * v;
    #pragma unroll
    for (int o = 16; o > 0; o >>= 1) {
        s  += __shfl_xor_sync(0xffffffffu, s,  o);
        sq += __shfl_xor_sync(0xffffffffu, sq, o);
    }
    __shared__ float sh_s[8], sh_sq[8], sh_stats[2];
    int warp = c >> 5, lane = c & 31;
    if (lane == 0) { sh_s[warp] = s; sh_sq[warp] = sq; }
    __syncthreads();
    if (warp == 0) {
        float a = (lane < 8) ? sh_s[lane]  : 0.f;
        float b = (lane < 8) ? sh_sq[lane] : 0.f;
        #pragma unroll
        for (int o = 4; o > 0; o >>= 1) {
            a += __shfl_xor_sync(0xffffffffu, a, o);
            b += __shfl_xor_sync(0xffffffffu, b, o);
        }
        if (lane == 0) {
            float mu  = a * (1.f / C_);
            float var = b * (1.f / C_) - mu * mu;
            sh_stats[0] = mu;
            sh_stats[1] = rsqrtf(var + 1e-5f);
        }
    }
    __syncthreads();
    out[idx] = (v - sh_stats[0]) * sh_stats[1] * gamma[c] + beta[c];
}

// ====================== GEMM  C = alpha * A * B^T (+bias) ====================
// A: MxK row-major, Bm: NxK row-major. 128x128 tile, BK=16, 256 thr, 8x8/thr.
__device__ __forceinline__ void gemm_abt(const float* __restrict__ A,
                                         const float* __restrict__ Bm,
                                         float* __restrict__ Cm,
                                         int N, int K, float alpha,
                                         const float* __restrict__ bias) {
    __shared__ float As[16][132];
    __shared__ float Bs[16][132];

    const int tid = threadIdx.x;
    const int tx  = tid & 15;      // n-dim
    const int ty  = tid >> 4;      // m-dim
    const int m0  = blockIdx.x * 128;
    const int n0  = blockIdx.y * 128;

    float acc[8][8];
    #pragma unroll
    for (int i = 0; i < 8; i++)
        #pragma unroll
        for (int j = 0; j < 8; j++) acc[i][j] = 0.f;

    for (int k0 = 0; k0 < K; k0 += 16) {
        #pragma unroll
        for (int i = 0; i < 2; i++) {
            int idx = tid + i * 256;           // 0..511
            int row = idx >> 2;                // 0..127
            int c4  = (idx & 3) * 4;           // 0,4,8,12
            float4 va = *(const float4*)&A [(size_t)(m0 + row) * K + k0 + c4];
            As[c4 + 0][row] = va.x; As[c4 + 1][row] = va.y;
            As[c4 + 2][row] = va.z; As[c4 + 3][row] = va.w;
            float4 vb = *(const float4*)&Bm[(size_t)(n0 + row) * K + k0 + c4];
            Bs[c4 + 0][row] = vb.x; Bs[c4 + 1][row] = vb.y;
            Bs[c4 + 2][row] = vb.z; Bs[c4 + 3][row] = vb.w;
        }
        __syncthreads();
        #pragma unroll
        for (int kk = 0; kk < 16; kk++) {
            float a[8], b[8];
            *(float4*)(a)     = *(const float4*)&As[kk][ty * 8];
            *(float4*)(a + 4) = *(const float4*)&As[kk][ty * 8 + 4];
            *(float4*)(b)     = *(const float4*)&Bs[kk][tx * 8];
            *(float4*)(b + 4) = *(const float4*)&Bs[kk][tx * 8 + 4];
            #pragma unroll
            for (int i = 0; i < 8; i++)
                #pragma unroll
                for (int j = 0; j < 8; j++)
                    acc[i][j] = fmaf(a[i], b[j], acc[i][j]);
        }
        __syncthreads();
    }

    #pragma unroll
    for (int i = 0; i < 8; i++) {
        int m = m0 + ty * 8 + i;
        #pragma unroll
        for (int j = 0; j < 8; j += 4) {
            int n = n0 + tx * 8 + j;
            float4 r;
            r.x = alpha * acc[i][j + 0];
            r.y = alpha * acc[i][j + 1];
            r.z = alpha * acc[i][j + 2];
            r.w = alpha * acc[i][j + 3];
            if (bias) {
                r.x += bias[n + 0]; r.y += bias[n + 1];
                r.z += bias[n + 2]; r.w += bias[n + 3];
            }
            *(float4*)&Cm[(size_t)m * N + n] = r;
        }
    }
}

// QKV projections: grid (128, 2, 3)
__global__ void __launch_bounds__(256) qkv_kernel(const float* __restrict__ gn,
                                                  const float* __restrict__ Wq,
                                                  const float* __restrict__ bq,
                                                  const float* __restrict__ Wk,
                                                  const float* __restrict__ bk,
                                                  const float* __restrict__ Wv,
                                                  const float* __restrict__ bv) {
    const float* W; const float* bias; float* out;
    if (blockIdx.z == 0)      { W = Wq; bias = bq; out = g_q; }
    else if (blockIdx.z == 1) { W = Wk; bias = bk; out = g_k; }
    else                      { W = Wv; bias = bv; out = g_v; }
    gemm_abt(gn, W, out, C_, C_, 1.0f, bias);
}

// Scores: S[b,t,s] = (1/16) * <q_t, k_s>. grid (32, 32, 4)
__global__ void __launch_bounds__(256) scores_kernel() {
    int b = blockIdx.z;
    gemm_abt(g_q + (size_t)b * T_ * C_,
             g_k + (size_t)b * T_ * C_,
             g_s + (size_t)b * T_ * T_,
             T_, C_, 0.0625f, nullptr);
}

// =============================== Softmax =====================================
// one block per (b,t) row of length 4096, in place on g_s
__global__ void __launch_bounds__(256) softmax_kernel() {
    float* row = g_s + (size_t)blockIdx.x * T_;
    const int tid = threadIdx.x;

    float4 v[4];
    #pragma unroll
    for (int i = 0; i < 4; i++)
        v[i] = *(float4*)&row[i * 1024 + tid * 4];

    float mx = -1e30f;
    #pragma unroll
    for (int i = 0; i < 4; i++) {
        mx = fmaxf(mx, fmaxf(fmaxf(v[i].x, v[i].y), fmaxf(v[i].z, v[i].w)));
    }
    __shared__ float sh[8], sh_b;
    int warp = tid >> 5, lane = tid & 31;
    #pragma unroll
    for (int o = 16; o > 0; o >>= 1) mx = fmaxf(mx, __shfl_xor_sync(0xffffffffu, mx, o));
    if (lane == 0) sh[warp] = mx;
    __syncthreads();
    if (warp == 0) {
        float a = (lane < 8) ? sh[lane] : -1e30f;
        #pragma unroll
        for (int o = 4; o > 0; o >>= 1) a = fmaxf(a, __shfl_xor_sync(0xffffffffu, a, o));
        if (lane == 0) sh_b = a;
    }
    __syncthreads();
    mx = sh_b;

    float sum = 0.f;
    #pragma unroll
    for (int i = 0; i < 4; i++) {
        v[i].x = __expf(v[i].x - mx); sum += v[i].x;
        v[i].y = __expf(v[i].y - mx); sum += v[i].y;
        v[i].z = __expf(v[i].z - mx); sum += v[i].z;
        v[i].w = __expf(v[i].w - mx); sum += v[i].w;
    }
    #pragma unroll
    for (int o = 16; o > 0; o >>= 1) sum += __shfl_xor_sync(0xffffffffu, sum, o);
    __syncthreads();
    if (lane == 0) sh[warp] = sum;
    __syncthreads();
    if (warp == 0) {
        float a = (lane < 8) ? sh[lane] : 0.f;
        #pragma unroll
        for (int o = 4; o > 0; o >>= 1) a += __shfl_xor_sync(0xffffffffu, a, o);
        if (lane == 0) sh_b = a;
    }
    __syncthreads();
    float inv = 1.f / sh_b;

    #pragma unroll
    for (int i = 0; i < 4; i++) {
        v[i].x *= inv; v[i].y *= inv; v[i].z *= inv; v[i].w *= inv;
        *(float4*)&row[i * 1024 + tid * 4] = v[i];
    }
}

// ============= Output: out[b,s,c] = x[b,s,c] + sum_t P[b,t,s]*V[b,t,c] =======
// C = A^T * B with A = probs (T x T, [t][s]), B = V (T x C). grid (32, 2, 4)
__global__ void __launch_bounds__(256) av_kernel(const float* __restrict__ x,
                                                 float* __restrict__ out) {
    const int b = blockIdx.z;
    const float* A = g_s + (size_t)b * T_ * T_;
    const float* V = g_v + (size_t)b * T_ * C_;

    __shared__ float As[16][128];   // [kt][s]
    __shared__ float Bs[16][128];   // [kt][c]

    const int tid = threadIdx.x;
    const int tx  = tid & 15;       // c-dim
    const int ty  = tid >> 4;       // s-dim
    const int s0  = blockIdx.x * 128;
    const int n0  = blockIdx.y * 128;

    float acc[8][8];
    #pragma unroll
    for (int i = 0; i < 8; i++)
        #pragma unroll
        for (int j = 0; j < 8; j++) acc[i][j] = 0.f;

    for (int k0 = 0; k0 < T_; k0 += 16) {
        #pragma unroll
        for (int i = 0; i < 2; i++) {
            int idx = tid + i * 256;        // 0..511
            int row = idx >> 5;             // 0..15  (kt)
            int c4  = (idx & 31) * 4;       // 0..124
            *(float4*)&As[row][c4] = *(const float4*)&A[(size_t)(k0 + row) * T_ + s0 + c4];
            *(float4*)&Bs[row][c4] = *(const float4*)&V[(size_t)(k0 + row) * C_ + n0 + c4];
        }
        __syncthreads();
        #pragma unroll
        for (int kk = 0; kk < 16; kk++) {
            float a[8], bb[8];
            *(float4*)(a)      = *(const float4*)&As[kk][ty * 8];
            *(float4*)(a + 4)  = *(const float4*)&As[kk][ty * 8 + 4];
            *(float4*)(bb)     = *(const float4*)&Bs[kk][tx * 8];
            *(float4*)(bb + 4) = *(const float4*)&Bs[kk][tx * 8 + 4];
            #pragma unroll
            for (int i = 0; i < 8; i++)
                #pragma unroll
                for (int j = 0; j < 8; j++)
                    acc[i][j] = fmaf(a[i], bb[j], acc[i][j]);
        }
        __syncthreads();
    }

    #pragma unroll
    for (int i = 0; i < 8; i++) {
        int s = s0 + ty * 8 + i;
        size_t base = ((size_t)b * T_ + s) * C_;
        #pragma unroll
        for (int j = 0; j < 8; j += 4) {
            int c = n0 + tx * 8 + j;
            float4 xr = *(const float4*)&x[base + c];
            float4 r;
            r.x = xr.x + acc[i][j + 0];
            r.y = xr.y + acc[i][j + 1];
            r.z = xr.z + acc[i][j + 2];
            r.w = xr.w + acc[i][j + 3];
            *(float4*)&out[base + c] = r;
        }
    }
}

// ================================ launch =====================================
extern "C" void kernel_launch(void* const* d_in, const int* in_sizes, int n_in,
                              void* d_out, int out_size) {
    const float* x     = (const float*)d_in[0];
    const float* gamma = (const float*)d_in[1];
    const float* beta  = (const float*)d_in[2];
    const float* Wq    = (const float*)d_in[3];
    const float* bq    = (const float*)d_in[4];
    const float* Wk    = (const float*)d_in[5];
    const float* bk    = (const float*)d_in[6];
    const float* Wv    = (const float*)d_in[7];
    const float* bv    = (const float*)d_in[8];
    float* out = (float*)d_out;

    float* gn;
    cudaGetSymbolAddress((void**)&gn, g_gn);

    ln_kernel<<<NTOK, 256>>>(x, gamma, beta, gn);
    qkv_kernel<<<dim3(NTOK / 128, C_ / 128, 3), 256>>>(gn, Wq, bq, Wk, bk, Wv, bv);
    scores_kernel<<<dim3(T_ / 128, T_ / 128, B_), 256>>>();
    softmax_kernel<<<NTOK, 256>>>();
    av_kernel<<<dim3(T_ / 128, C_ / 128, B_), 256>>>(x, out);
}

// round 2
// speedup vs baseline: 1.7829x; 1.7829x over previous
#include <cuda_runtime.h>
#include <cstdint>

#define B_   4
#define T_   4096
#define C_   256
#define NTOK (B_ * T_)   // 16384

// ---------------- scratch (static device arrays; no allocation) --------------
__device__ float g_gn[NTOK * C_];
__device__ float g_q [NTOK * C_];
__device__ float g_k [NTOK * C_];
__device__ float g_v [NTOK * C_];
__device__ float g_s [(size_t)B_ * T_ * T_];   // 268 MB attention scores/probs

// ---------------- helpers ----------------------------------------------------
__device__ __forceinline__ float to_tf32(float x) {
    float y;
    asm("cvt.rna.tf32.f32 %0, %1;" : "=f"(y) : "f"(x));
    return y;
}

__device__ __forceinline__ void mma_tf32(float c[4],
                                         uint32_t a0, uint32_t a1, uint32_t a2, uint32_t a3,
                                         uint32_t b0, uint32_t b1) {
    asm volatile(
        "mma.sync.aligned.m16n8k8.row.col.f32.tf32.tf32.f32 "
        "{%0,%1,%2,%3}, {%4,%5,%6,%7}, {%8,%9}, {%0,%1,%2,%3};"
        : "+f"(c[0]), "+f"(c[1]), "+f"(c[2]), "+f"(c[3])
        : "r"(a0), "r"(a1), "r"(a2), "r"(a3), "r"(b0), "r"(b1));
}

// =============================== LayerNorm ==================================
__global__ void __launch_bounds__(256) ln_kernel(const float* __restrict__ x,
                                                 const float* __restrict__ gamma,
                                                 const float* __restrict__ beta,
                                                 float* __restrict__ out) {
    int t = blockIdx.x;
    int c = threadIdx.x;
    size_t idx = (size_t)t * C_ + c;
    float v = x[idx];
    float s = v, sq = v * v;
    #pragma unroll
    for (int o = 16; o > 0; o >>= 1) {
        s  += __shfl_xor_sync(0xffffffffu, s,  o);
        sq += __shfl_xor_sync(0xffffffffu, sq, o);
    }
    __shared__ float sh_s[8], sh_sq[8], sh_stats[2];
    int warp = c >> 5, lane = c & 31;
    if (lane == 0) { sh_s[warp] = s; sh_sq[warp] = sq; }
    __syncthreads();
    if (warp == 0) {
        float a = (lane < 8) ? sh_s[lane]  : 0.f;
        float b = (lane < 8) ? sh_sq[lane] : 0.f;
        #pragma unroll
        for (int o = 4; o > 0; o >>= 1) {
            a += __shfl_xor_sync(0xffffffffu, a, o);
            b += __shfl_xor_sync(0xffffffffu, b, o);
        }
        if (lane == 0) {
            float mu  = a * (1.f / C_);
            float var = b * (1.f / C_) - mu * mu;
            sh_stats[0] = mu;
            sh_stats[1] = rsqrtf(var + 1e-5f);
        }
    }
    __syncthreads();
    out[idx] = (v - sh_stats[0]) * sh_stats[1] * gamma[c] + beta[c];
}

// ================= tf32 GEMM  C = alpha * A * B^T (+bias) ===================
// A: MxK row-major, Bm: NxK row-major. Block tile 128x128, BK=16.
// 8 warps: wm = wid>>1 (4 x 32 rows), wn = wid&1 (2 x 64 cols).
__device__ __forceinline__ void gemm_abt_tf32(const float* __restrict__ A,
                                              const float* __restrict__ Bm,
                                              float* __restrict__ Cm,
                                              int N, int K, float alpha,
                                              const float* __restrict__ bias) {
    __shared__ float As[16][132];   // [k][m]
    __shared__ float Bs[16][132];   // [k][n]

    const int tid  = threadIdx.x;
    const int lane = tid & 31;
    const int wid  = tid >> 5;
    const int wm   = wid >> 1;      // 0..3
    const int wn   = wid & 1;       // 0..1
    const int g    = lane >> 2;     // 0..7
    const int tig  = lane & 3;      // 0..3
    const int m0   = blockIdx.x * 128;
    const int n0   = blockIdx.y * 128;

    float acc[2][8][4];
    #pragma unroll
    for (int mi = 0; mi < 2; mi++)
        #pragma unroll
        for (int ni = 0; ni < 8; ni++)
            #pragma unroll
            for (int r = 0; r < 4; r++) acc[mi][ni][r] = 0.f;

    for (int k0 = 0; k0 < K; k0 += 16) {
        // load & transpose tiles into [k][m]/[k][n], converting to tf32
        #pragma unroll
        for (int i = 0; i < 2; i++) {
            int idx = tid + i * 256;          // 0..511
            int row = idx >> 2;               // 0..127
            int c4  = (idx & 3) * 4;          // 0,4,8,12
            float4 va = *(const float4*)&A [(size_t)(m0 + row) * K + k0 + c4];
            As[c4 + 0][row] = to_tf32(va.x); As[c4 + 1][row] = to_tf32(va.y);
            As[c4 + 2][row] = to_tf32(va.z); As[c4 + 3][row] = to_tf32(va.w);
            float4 vb = *(const float4*)&Bm[(size_t)(n0 + row) * K + k0 + c4];
            Bs[c4 + 0][row] = to_tf32(vb.x); Bs[c4 + 1][row] = to_tf32(vb.y);
            Bs[c4 + 2][row] = to_tf32(vb.z); Bs[c4 + 3][row] = to_tf32(vb.w);
        }
        __syncthreads();

        #pragma unroll
        for (int ks = 0; ks < 16; ks += 8) {
            uint32_t a[2][4], b[8][2];
            #pragma unroll
            for (int mi = 0; mi < 2; mi++) {
                int mo = wm * 32 + mi * 16;
                a[mi][0] = __float_as_uint(As[ks + tig    ][mo + g    ]);
                a[mi][1] = __float_as_uint(As[ks + tig    ][mo + g + 8]);
                a[mi][2] = __float_as_uint(As[ks + tig + 4][mo + g    ]);
                a[mi][3] = __float_as_uint(As[ks + tig + 4][mo + g + 8]);
            }
            #pragma unroll
            for (int ni = 0; ni < 8; ni++) {
                int no = wn * 64 + ni * 8;
                b[ni][0] = __float_as_uint(Bs[ks + tig    ][no + g]);
                b[ni][1] = __float_as_uint(Bs[ks + tig + 4][no + g]);
            }
            #pragma unroll
            for (int mi = 0; mi < 2; mi++)
                #pragma unroll
                for (int ni = 0; ni < 8; ni++)
                    mma_tf32(acc[mi][ni], a[mi][0], a[mi][1], a[mi][2], a[mi][3],
                             b[ni][0], b[ni][1]);
        }
        __syncthreads();
    }

    // epilogue: D layout c0:(g,2t) c1:(g,2t+1) c2:(g+8,2t) c3:(g+8,2t+1)
    #pragma unroll
    for (int mi = 0; mi < 2; mi++) {
        int row = m0 + wm * 32 + mi * 16 + g;
        #pragma unroll
        for (int ni = 0; ni < 8; ni++) {
            int col = n0 + wn * 64 + ni * 8 + tig * 2;
            float bx = bias ? bias[col]     : 0.f;
            float by = bias ? bias[col + 1] : 0.f;
            float2 r0 = make_float2(alpha * acc[mi][ni][0] + bx,
                                    alpha * acc[mi][ni][1] + by);
            float2 r1 = make_float2(alpha * acc[mi][ni][2] + bx,
                                    alpha * acc[mi][ni][3] + by);
            *(float2*)&Cm[(size_t)row * N + col]       = r0;
            *(float2*)&Cm[(size_t)(row + 8) * N + col] = r1;
        }
    }
}

// QKV projections: grid (128, 2, 3)
__global__ void __launch_bounds__(256) qkv_kernel(const float* __restrict__ gn,
                                                  const float* __restrict__ Wq,
                                                  const float* __restrict__ bq,
                                                  const float* __restrict__ Wk,
                                                  const float* __restrict__ bk,
                                                  const float* __restrict__ Wv,
                                                  const float* __restrict__ bv) {
    const float* W; const float* bias; float* out;
    if (blockIdx.z == 0)      { W = Wq; bias = bq; out = g_q; }
    else if (blockIdx.z == 1) { W = Wk; bias = bk; out = g_k; }
    else                      { W = Wv; bias = bv; out = g_v; }
    gemm_abt_tf32(gn, W, out, C_, C_, 1.0f, bias);
}

// Scores: S[b,t,s] = (1/16) * <q_t, k_s>. grid (32, 32, 4)
__global__ void __launch_bounds__(256) scores_kernel() {
    int b = blockIdx.z;
    gemm_abt_tf32(g_q + (size_t)b * T_ * C_,
                  g_k + (size_t)b * T_ * C_,
                  g_s + (size_t)b * T_ * T_,
                  T_, C_, 0.0625f, nullptr);
}

// =============================== Softmax =====================================
__global__ void __launch_bounds__(256) softmax_kernel() {
    float* row = g_s + (size_t)blockIdx.x * T_;
    const int tid = threadIdx.x;

    float4 v[4];
    #pragma unroll
    for (int i = 0; i < 4; i++)
        v[i] = *(float4*)&row[i * 1024 + tid * 4];

    float mx = -1e30f;
    #pragma unroll
    for (int i = 0; i < 4; i++)
        mx = fmaxf(mx, fmaxf(fmaxf(v[i].x, v[i].y), fmaxf(v[i].z, v[i].w)));

    __shared__ float sh[8], sh_b;
    int warp = tid >> 5, lane = tid & 31;
    #pragma unroll
    for (int o = 16; o > 0; o >>= 1) mx = fmaxf(mx, __shfl_xor_sync(0xffffffffu, mx, o));
    if (lane == 0) sh[warp] = mx;
    __syncthreads();
    if (warp == 0) {
        float a = (lane < 8) ? sh[lane] : -1e30f;
        #pragma unroll
        for (int o = 4; o > 0; o >>= 1) a = fmaxf(a, __shfl_xor_sync(0xffffffffu, a, o));
        if (lane == 0) sh_b = a;
    }
    __syncthreads();
    mx = sh_b;

    float sum = 0.f;
    #pragma unroll
    for (int i = 0; i < 4; i++) {
        v[i].x = __expf(v[i].x - mx); sum += v[i].x;
        v[i].y = __expf(v[i].y - mx); sum += v[i].y;
        v[i].z = __expf(v[i].z - mx); sum += v[i].z;
        v[i].w = __expf(v[i].w - mx); sum += v[i].w;
    }
    #pragma unroll
    for (int o = 16; o > 0; o >>= 1) sum += __shfl_xor_sync(0xffffffffu, sum, o);
    __syncthreads();
    if (lane == 0) sh[warp] = sum;
    __syncthreads();
    if (warp == 0) {
        float a = (lane < 8) ? sh[lane] : 0.f;
        #pragma unroll
        for (int o = 4; o > 0; o >>= 1) a += __shfl_xor_sync(0xffffffffu, a, o);
        if (lane == 0) sh_b = a;
    }
    __syncthreads();
    float inv = 1.f / sh_b;

    #pragma unroll
    for (int i = 0; i < 4; i++) {
        v[i].x *= inv; v[i].y *= inv; v[i].z *= inv; v[i].w *= inv;
        *(float4*)&row[i * 1024 + tid * 4] = v[i];
    }
}

// ===== Output: out[b,s,c] = x[b,s,c] + sum_t P[b,t,s]*V[b,t,c]  (tf32 mma) ===
// A^T GEMM: As[k=t][m=s] = P[t][s] (direct copy), Bs[k=t][n=c] = V[t][c].
// grid (32, 2, 4)
__global__ void __launch_bounds__(256) av_kernel(const float* __restrict__ x,
                                                 float* __restrict__ out) {
    const int b = blockIdx.z;
    const float* P = g_s + (size_t)b * T_ * T_;
    const float* V = g_v + (size_t)b * T_ * C_;

    __shared__ float As[16][132];   // [t][s]
    __shared__ float Bs[16][132];   // [t][c]

    const int tid  = threadIdx.x;
    const int lane = tid & 31;
    const int wid  = tid >> 5;
    const int wm   = wid >> 1;
    const int wn   = wid & 1;
    const int g    = lane >> 2;
    const int tig  = lane & 3;
    const int s0   = blockIdx.x * 128;
    const int n0   = blockIdx.y * 128;

    float acc[2][8][4];
    #pragma unroll
    for (int mi = 0; mi < 2; mi++)
        #pragma unroll
        for (int ni = 0; ni < 8; ni++)
            #pragma unroll
            for (int r = 0; r < 4; r++) acc[mi][ni][r] = 0.f;

    for (int k0 = 0; k0 < T_; k0 += 16) {
        // both tiles are already [k][*] in global memory: direct float4 copies
        #pragma unroll
        for (int i = 0; i < 2; i++) {
            int idx  = tid + i * 256;        // 0..511
            int row  = idx >> 5;             // 0..15
            int col4 = (idx & 31) * 4;       // 0..124
            float4 va = *(const float4*)&P[(size_t)(k0 + row) * T_ + s0 + col4];
            va.x = to_tf32(va.x); va.y = to_tf32(va.y);
            va.z = to_tf32(va.z); va.w = to_tf32(va.w);
            *(float4*)&As[row][col4] = va;
            float4 vb = *(const float4*)&V[(size_t)(k0 + row) * C_ + n0 + col4];
            vb.x = to_tf32(vb.x); vb.y = to_tf32(vb.y);
            vb.z = to_tf32(vb.z); vb.w = to_tf32(vb.w);
            *(float4*)&Bs[row][col4] = vb;
        }
        __syncthreads();

        #pragma unroll
        for (int ks = 0; ks < 16; ks += 8) {
            uint32_t a[2][4], bb[8][2];
            #pragma unroll
            for (int mi = 0; mi < 2; mi++) {
                int mo = wm * 32 + mi * 16;
                a[mi][0] = __float_as_uint(As[ks + tig    ][mo + g    ]);
                a[mi][1] = __float_as_uint(As[ks + tig    ][mo + g + 8]);
                a[mi][2] = __float_as_uint(As[ks + tig + 4][mo + g    ]);
                a[mi][3] = __float_as_uint(As[ks + tig + 4][mo + g + 8]);
            }
            #pragma unroll
            for (int ni = 0; ni < 8; ni++) {
                int no = wn * 64 + ni * 8;
                bb[ni][0] = __float_as_uint(Bs[ks + tig    ][no + g]);
                bb[ni][1] = __float_as_uint(Bs[ks + tig + 4][no + g]);
            }
            #pragma unroll
            for (int mi = 0; mi < 2; mi++)
                #pragma unroll
                for (int ni = 0; ni < 8; ni++)
                    mma_tf32(acc[mi][ni], a[mi][0], a[mi][1], a[mi][2], a[mi][3],
                             bb[ni][0], bb[ni][1]);
        }
        __syncthreads();
    }

    #pragma unroll
    for (int mi = 0; mi < 2; mi++) {
        int s = s0 + wm * 32 + mi * 16 + g;
        size_t base0 = ((size_t)b * T_ + s) * C_;
        size_t base1 = ((size_t)b * T_ + s + 8) * C_;
        #pragma unroll
        for (int ni = 0; ni < 8; ni++) {
            int c = n0 + wn * 64 + ni * 8 + tig * 2;
            float2 xr0 = *(const float2*)&x[base0 + c];
            float2 xr1 = *(const float2*)&x[base1 + c];
            float2 r0 = make_float2(xr0.x + acc[mi][ni][0], xr0.y + acc[mi][ni][1]);
            float2 r1 = make_float2(xr1.x + acc[mi][ni][2], xr1.y + acc[mi][ni][3]);
            *(float2*)&out[base0 + c] = r0;
            *(float2*)&out[base1 + c] = r1;
        }
    }
}

// ================================ launch =====================================
extern "C" void kernel_launch(void* const* d_in, const int* in_sizes, int n_in,
                              void* d_out, int out_size) {
    const float* x     = (const float*)d_in[0];
    const float* gamma = (const float*)d_in[1];
    const float* beta  = (const float*)d_in[2];
    const float* Wq    = (const float*)d_in[3];
    const float* bq    = (const float*)d_in[4];
    const float* Wk    = (const float*)d_in[5];
    const float* bk    = (const float*)d_in[6];
    const float* Wv    = (const float*)d_in[7];
    const float* bv    = (const float*)d_in[8];
    float* out = (float*)d_out;

    float* gn;
    cudaGetSymbolAddress((void**)&gn, g_gn);

    ln_kernel<<<NTOK, 256>>>(x, gamma, beta, gn);
    qkv_kernel<<<dim3(NTOK / 128, C_ / 128, 3), 256>>>(gn, Wq, bq, Wk, bk, Wv, bv);
    scores_kernel<<<dim3(T_ / 128, T_ / 128, B_), 256>>>();
    softmax_kernel<<<NTOK, 256>>>();
    av_kernel<<<dim3(T_ / 128, C_ / 128, B_), 256>>>(x, out);
}

// round 3
// speedup vs baseline: 4.0612x; 2.2779x over previous
#include <cuda_runtime.h>
#include <cuda_bf16.h>
#include <cstdint>

#define B_   4
#define T_   4096
#define C_   256
#define NTOK (B_ * T_)   // 16384

// ---------------- scratch (static device arrays; no allocation) --------------
__device__ float g_gn[NTOK * C_];
__device__ float g_q [NTOK * C_];
__device__ float g_k [NTOK * C_];
__device__ float g_v [NTOK * C_];
__device__ __nv_bfloat16 g_e [(size_t)B_ * T_ * T_];   // E^T: [b][s][t], bf16
__device__ __nv_bfloat16 g_vt[(size_t)B_ * C_ * T_];   // V'^T: [b][c][t], bf16
__device__ float g_zpart[NTOK * 32];                   // per (b,t): 32 s-tile partials
__device__ float g_zinv [NTOK];

// ---------------- mma / ldmatrix helpers -------------------------------------
__device__ __forceinline__ void mma_tf32(float c[4],
                                         uint32_t a0, uint32_t a1, uint32_t a2, uint32_t a3,
                                         uint32_t b0, uint32_t b1) {
    asm volatile(
        "mma.sync.aligned.m16n8k8.row.col.f32.tf32.tf32.f32 "
        "{%0,%1,%2,%3}, {%4,%5,%6,%7}, {%8,%9}, {%0,%1,%2,%3};"
        : "+f"(c[0]), "+f"(c[1]), "+f"(c[2]), "+f"(c[3])
        : "r"(a0), "r"(a1), "r"(a2), "r"(a3), "r"(b0), "r"(b1));
}

__device__ __forceinline__ void mma_bf16(float c[4],
                                         uint32_t a0, uint32_t a1, uint32_t a2, uint32_t a3,
                                         uint32_t b0, uint32_t b1) {
    asm volatile(
        "mma.sync.aligned.m16n8k16.row.col.f32.bf16.bf16.f32 "
        "{%0,%1,%2,%3}, {%4,%5,%6,%7}, {%8,%9}, {%0,%1,%2,%3};"
        : "+f"(c[0]), "+f"(c[1]), "+f"(c[2]), "+f"(c[3])
        : "r"(a0), "r"(a1), "r"(a2), "r"(a3), "r"(b0), "r"(b1));
}

__device__ __forceinline__ void ldsm4(uint32_t& r0, uint32_t& r1, uint32_t& r2, uint32_t& r3,
                                      uint32_t addr) {
    asm volatile("ldmatrix.sync.aligned.m8n8.x4.shared.b16 {%0,%1,%2,%3}, [%4];"
                 : "=r"(r0), "=r"(r1), "=r"(r2), "=r"(r3) : "r"(addr));
}

// =============================== LayerNorm ==================================
__global__ void __launch_bounds__(256) ln_kernel(const float* __restrict__ x,
                                                 const float* __restrict__ gamma,
                                                 const float* __restrict__ beta) {
    int t = blockIdx.x;
    int c = threadIdx.x;
    size_t idx = (size_t)t * C_ + c;
    float v = x[idx];
    float s = v, sq = v * v;
    #pragma unroll
    for (int o = 16; o > 0; o >>= 1) {
        s  += __shfl_xor_sync(0xffffffffu, s,  o);
        sq += __shfl_xor_sync(0xffffffffu, sq, o);
    }
    __shared__ float sh_s[8], sh_sq[8], sh_stats[2];
    int warp = c >> 5, lane = c & 31;
    if (lane == 0) { sh_s[warp] = s; sh_sq[warp] = sq; }
    __syncthreads();
    if (warp == 0) {
        float a = (lane < 8) ? sh_s[lane]  : 0.f;
        float b = (lane < 8) ? sh_sq[lane] : 0.f;
        #pragma unroll
        for (int o = 4; o > 0; o >>= 1) {
            a += __shfl_xor_sync(0xffffffffu, a, o);
            b += __shfl_xor_sync(0xffffffffu, b, o);
        }
        if (lane == 0) {
            float mu  = a * (1.f / C_);
            float var = b * (1.f / C_) - mu * mu;
            sh_stats[0] = mu;
            sh_stats[1] = rsqrtf(var + 1e-5f);
        }
    }
    __syncthreads();
    g_gn[idx] = (v - sh_stats[0]) * sh_stats[1] * gamma[c] + beta[c];
}

// ================= tf32 core: 128x128 tile, K=256, BK=32 =====================
// A: Mx256 row-major, Bm: Nx256 row-major (both stride 256). acc[2][8][4].
struct SmemT { float As[128][36]; float Bs[128][36]; };  // 36864 B

__device__ __forceinline__ void core_tf32(SmemT* sm,
                                          const float* __restrict__ A,
                                          const float* __restrict__ Bm,
                                          int m0, int n0,
                                          float acc[2][8][4]) {
    const int tid  = threadIdx.x;
    const int lane = tid & 31;
    const int wid  = tid >> 5;
    const int wm   = wid >> 1;
    const int wn   = wid & 1;

    #pragma unroll
    for (int mi = 0; mi < 2; mi++)
        #pragma unroll
        for (int ni = 0; ni < 8; ni++)
            #pragma unroll
            for (int r = 0; r < 4; r++) acc[mi][ni][r] = 0.f;

    // ldmatrix addresses (fixed per thread)
    uint32_t asB = (uint32_t)__cvta_generic_to_shared(&sm->As[0][0]);
    uint32_t bsB = (uint32_t)__cvta_generic_to_shared(&sm->Bs[0][0]);
    const int arow = (lane & 7) + (lane & 8);
    const int acol = (lane & 16) ? 4 : 0;
    uint32_t aAddr[2];
    #pragma unroll
    for (int mi = 0; mi < 2; mi++)
        aAddr[mi] = asB + (uint32_t)(((wm * 32 + mi * 16 + arow) * 36 + acol) * 4);
    const int brow = (lane & 7) + ((lane & 16) ? 8 : 0);
    const int bcol = (lane & 8) ? 4 : 0;
    uint32_t bAddr[4];
    #pragma unroll
    for (int p = 0; p < 4; p++)
        bAddr[p] = bsB + (uint32_t)(((wn * 64 + p * 16 + brow) * 36 + bcol) * 4);

    // load indices
    const int lrow = tid >> 3;
    const int lc4  = (tid & 7) * 4;

    float4 bufA[4], bufB[4];
    #pragma unroll
    for (int i = 0; i < 4; i++) {
        int row = lrow + i * 32;
        bufA[i] = *(const float4*)&A [(size_t)(m0 + row) * 256 + lc4];
        bufB[i] = *(const float4*)&Bm[(size_t)(n0 + row) * 256 + lc4];
    }
    #pragma unroll
    for (int i = 0; i < 4; i++) {
        int row = lrow + i * 32;
        *(float4*)&sm->As[row][lc4] = bufA[i];
        *(float4*)&sm->Bs[row][lc4] = bufB[i];
    }
    __syncthreads();

    for (int kt = 0; kt < 8; kt++) {
        if (kt < 7) {
            int kb = (kt + 1) * 32;
            #pragma unroll
            for (int i = 0; i < 4; i++) {
                int row = lrow + i * 32;
                bufA[i] = *(const float4*)&A [(size_t)(m0 + row) * 256 + kb + lc4];
                bufB[i] = *(const float4*)&Bm[(size_t)(n0 + row) * 256 + kb + lc4];
            }
        }
        #pragma unroll
        for (int ks_i = 0; ks_i < 4; ks_i++) {
            const uint32_t koff = ks_i * 32;   // 8 f32 = 32 bytes
            uint32_t a[2][4];
            #pragma unroll
            for (int mi = 0; mi < 2; mi++)
                ldsm4(a[mi][0], a[mi][1], a[mi][2], a[mi][3], aAddr[mi] + koff);
            #pragma unroll
            for (int p = 0; p < 4; p++) {
                uint32_t b0, b1, b2, b3;
                ldsm4(b0, b1, b2, b3, bAddr[p] + koff);
                #pragma unroll
                for (int mi = 0; mi < 2; mi++) {
                    mma_tf32(acc[mi][2 * p],     a[mi][0], a[mi][1], a[mi][2], a[mi][3], b0, b1);
                    mma_tf32(acc[mi][2 * p + 1], a[mi][0], a[mi][1], a[mi][2], a[mi][3], b2, b3);
                }
            }
        }
        __syncthreads();
        if (kt < 7) {
            #pragma unroll
            for (int i = 0; i < 4; i++) {
                int row = lrow + i * 32;
                *(float4*)&sm->As[row][lc4] = bufA[i];
                *(float4*)&sm->Bs[row][lc4] = bufB[i];
            }
            __syncthreads();
        }
    }
}

// =============================== QKV ==========================================
__global__ void __launch_bounds__(256) qkv_kernel(const float* __restrict__ Wq,
                                                  const float* __restrict__ bq,
                                                  const float* __restrict__ Wk,
                                                  const float* __restrict__ bk,
                                                  const float* __restrict__ Wv,
                                                  const float* __restrict__ bv) {
    __shared__ SmemT sm;
    const float* W; const float* bias; float* out;
    if (blockIdx.z == 0)      { W = Wq; bias = bq; out = g_q; }
    else if (blockIdx.z == 1) { W = Wk; bias = bk; out = g_k; }
    else                      { W = Wv; bias = bv; out = g_v; }

    float acc[2][8][4];
    core_tf32(&sm, g_gn, W, blockIdx.x * 128, blockIdx.y * 128, acc);

    const int lane = threadIdx.x & 31, wid = threadIdx.x >> 5;
    const int wm = wid >> 1, wn = wid & 1, g = lane >> 2, tig = lane & 3;
    const int m0 = blockIdx.x * 128, n0 = blockIdx.y * 128;
    #pragma unroll
    for (int mi = 0; mi < 2; mi++) {
        int row = m0 + wm * 32 + mi * 16 + g;
        #pragma unroll
        for (int ni = 0; ni < 8; ni++) {
            int col = n0 + wn * 64 + ni * 8 + tig * 2;
            float bx = bias[col], by = bias[col + 1];
            *(float2*)&out[(size_t)row * 256 + col] =
                make_float2(acc[mi][ni][0] + bx, acc[mi][ni][1] + by);
            *(float2*)&out[(size_t)(row + 8) * 256 + col] =
                make_float2(acc[mi][ni][2] + bx, acc[mi][ni][3] + by);
        }
    }
}

// ====================== scores + exp + rowsum + E^T (bf16) ====================
__global__ void __launch_bounds__(256) scores_kernel() {
    __shared__ union {
        SmemT g;
        unsigned short et[128][136];   // [s_local][t_local], 34816 B
        float rowsum[128];
    } sm;

    const int bz = blockIdx.z;
    const int t0 = blockIdx.x * 128;   // m: query/row index (softmax rows)
    const int s0 = blockIdx.y * 128;   // n: key/col index
    const float* Q = g_q + (size_t)bz * T_ * C_;
    const float* K = g_k + (size_t)bz * T_ * C_;

    float acc[2][8][4];
    core_tf32(&sm.g, Q, K, t0, s0, acc);

    const int tid = threadIdx.x;
    const int lane = tid & 31, wid = tid >> 5;
    const int wm = wid >> 1, wn = wid & 1, g = lane >> 2, tig = lane & 3;

    // exp(score / 16)
    #pragma unroll
    for (int mi = 0; mi < 2; mi++)
        #pragma unroll
        for (int ni = 0; ni < 8; ni++)
            #pragma unroll
            for (int r = 0; r < 4; r++)
                acc[mi][ni][r] = __expf(acc[mi][ni][r] * 0.0625f);

    // per-row (t) partial sums over this block's 128 s-columns
    __syncthreads();
    if (tid < 128) sm.rowsum[tid] = 0.f;
    __syncthreads();
    #pragma unroll
    for (int mi = 0; mi < 2; mi++) {
        float s0v = 0.f, s1v = 0.f;
        #pragma unroll
        for (int ni = 0; ni < 8; ni++) {
            s0v += acc[mi][ni][0] + acc[mi][ni][1];
            s1v += acc[mi][ni][2] + acc[mi][ni][3];
        }
        s0v += __shfl_xor_sync(0xffffffffu, s0v, 1);
        s0v += __shfl_xor_sync(0xffffffffu, s0v, 2);
        s1v += __shfl_xor_sync(0xffffffffu, s1v, 1);
        s1v += __shfl_xor_sync(0xffffffffu, s1v, 2);
        if (tig == 0) {
            atomicAdd(&sm.rowsum[wm * 32 + mi * 16 + g],     s0v);
            atomicAdd(&sm.rowsum[wm * 32 + mi * 16 + g + 8], s1v);
        }
    }
    __syncthreads();
    if (tid < 128)
        g_zpart[(size_t)(bz * T_ + t0 + tid) * 32 + blockIdx.y] = sm.rowsum[tid];
    __syncthreads();

    // stage transposed bf16 tile: et[s_local][t_local]
    #pragma unroll
    for (int mi = 0; mi < 2; mi++) {
        int r0 = wm * 32 + mi * 16 + g;
        #pragma unroll
        for (int ni = 0; ni < 8; ni++) {
            int col = wn * 64 + ni * 8 + tig * 2;
            sm.et[col][r0]         = __bfloat16_as_ushort(__float2bfloat16(acc[mi][ni][0]));
            sm.et[col + 1][r0]     = __bfloat16_as_ushort(__float2bfloat16(acc[mi][ni][1]));
            sm.et[col][r0 + 8]     = __bfloat16_as_ushort(__float2bfloat16(acc[mi][ni][2]));
            sm.et[col + 1][r0 + 8] = __bfloat16_as_ushort(__float2bfloat16(acc[mi][ni][3]));
        }
    }
    __syncthreads();

    // coalesced store E^T[b][s0+sl][t0 .. t0+127]
    #pragma unroll
    for (int i = 0; i < 8; i++) {
        int lin = tid + i * 256;
        int sl = lin >> 4, c8 = (lin & 15) * 8;
        uint4 d = *(uint4*)&sm.et[sl][c8];
        *(uint4*)&g_e[(size_t)(bz * T_ + s0 + sl) * T_ + t0 + c8] = d;
    }
}

// =============================== reduce Z → 1/Z ===============================
__global__ void __launch_bounds__(256) reduce_z_kernel() {
    int tok = blockIdx.x * 256 + threadIdx.x;
    float s = 0.f;
    #pragma unroll
    for (int j = 0; j < 32; j++) s += g_zpart[(size_t)tok * 32 + j];
    g_zinv[tok] = 1.f / s;
}

// ================= V'[c][t] = bf16( V[t][c] / Z_t ), transposed ==============
__global__ void __launch_bounds__(256) zv_kernel() {
    __shared__ unsigned short vs[128][136];   // [c_local][t_local]
    const int bz = blockIdx.z;
    const int t0 = blockIdx.x * 128;
    const int c0 = blockIdx.y * 128;
    const float* V = g_v + (size_t)bz * T_ * C_;
    const int tid = threadIdx.x;

    #pragma unroll
    for (int i = 0; i < 8; i++) {
        int lin = tid + i * 256;            // 0..2047
        int tl = lin >> 4, c8 = (lin & 15) * 8;
        float zi = g_zinv[bz * T_ + t0 + tl];
        float4 v0 = *(const float4*)&V[(size_t)(t0 + tl) * C_ + c0 + c8];
        float4 v1 = *(const float4*)&V[(size_t)(t0 + tl) * C_ + c0 + c8 + 4];
        vs[c8 + 0][tl] = __bfloat16_as_ushort(__float2bfloat16(v0.x * zi));
        vs[c8 + 1][tl] = __bfloat16_as_ushort(__float2bfloat16(v0.y * zi));
        vs[c8 + 2][tl] = __bfloat16_as_ushort(__float2bfloat16(v0.z * zi));
        vs[c8 + 3][tl] = __bfloat16_as_ushort(__float2bfloat16(v0.w * zi));
        vs[c8 + 4][tl] = __bfloat16_as_ushort(__float2bfloat16(v1.x * zi));
        vs[c8 + 5][tl] = __bfloat16_as_ushort(__float2bfloat16(v1.y * zi));
        vs[c8 + 6][tl] = __bfloat16_as_ushort(__float2bfloat16(v1.z * zi));
        vs[c8 + 7][tl] = __bfloat16_as_ushort(__float2bfloat16(v1.w * zi));
    }
    __syncthreads();
    #pragma unroll
    for (int i = 0; i < 8; i++) {
        int lin = tid + i * 256;
        int cl = lin >> 4, t8 = (lin & 15) * 8;
        uint4 d = *(uint4*)&vs[cl][t8];
        *(uint4*)&g_vt[(size_t)(bz * C_ + c0 + cl) * T_ + t0 + t8] = d;
    }
}

// ======= AV (bf16): out[b,s,c] = x[b,s,c] + sum_t E^T[s,t] * V'^T[c,t] =======
struct SmemAV { __nv_bfloat16 A[128][72]; __nv_bfloat16 Bv[128][72]; };  // 36864 B

__global__ void __launch_bounds__(256) av_kernel(const float* __restrict__ x,
                                                 float* __restrict__ out) {
    __shared__ SmemAV sm;
    const int bz = blockIdx.z;
    const int s0 = blockIdx.x * 128;
    const int c0 = blockIdx.y * 128;
    const __nv_bfloat16* Ea = g_e  + (size_t)bz * T_ * T_;
    const __nv_bfloat16* Va = g_vt + (size_t)bz * C_ * T_;

    const int tid = threadIdx.x;
    const int lane = tid & 31, wid = tid >> 5;
    const int wm = wid >> 1, wn = wid & 1, g = lane >> 2, tig = lane & 3;

    float acc[2][8][4];
    #pragma unroll
    for (int mi = 0; mi < 2; mi++)
        #pragma unroll
        for (int ni = 0; ni < 8; ni++)
            #pragma unroll
            for (int r = 0; r < 4; r++) acc[mi][ni][r] = 0.f;

    uint32_t asB = (uint32_t)__cvta_generic_to_shared(&sm.A[0][0]);
    uint32_t bsB = (uint32_t)__cvta_generic_to_shared(&sm.Bv[0][0]);
    const int arow = (lane & 7) + (lane & 8);
    const int acol = (lane & 16) ? 8 : 0;   // bf16 cols
    uint32_t aAddr[2];
    #pragma unroll
    for (int mi = 0; mi < 2; mi++)
        aAddr[mi] = asB + (uint32_t)(((wm * 32 + mi * 16 + arow) * 72 + acol) * 2);
    const int brow = (lane & 7) + ((lane & 16) ? 8 : 0);
    const int bcol = (lane & 8) ? 8 : 0;
    uint32_t bAddr[4];
    #pragma unroll
    for (int p = 0; p < 4; p++)
        bAddr[p] = bsB + (uint32_t)(((wn * 64 + p * 16 + brow) * 72 + bcol) * 2);

    const int lrow = tid >> 3;
    const int lc8  = (tid & 7) * 8;

    uint4 bufA[4], bufB[4];
    #pragma unroll
    for (int i = 0; i < 4; i++) {
        int row = lrow + i * 32;
        bufA[i] = *(const uint4*)&Ea[(size_t)(s0 + row) * T_ + lc8];
        bufB[i] = *(const uint4*)&Va[(size_t)(c0 + row) * T_ + lc8];
    }
    #pragma unroll
    for (int i = 0; i < 4; i++) {
        int row = lrow + i * 32;
        *(uint4*)&sm.A [row][lc8] = bufA[i];
        *(uint4*)&sm.Bv[row][lc8] = bufB[i];
    }
    __syncthreads();

    const int KT = T_ / 64;   // 64
    for (int kt = 0; kt < KT; kt++) {
        if (kt < KT - 1) {
            int kb = (kt + 1) * 64;
            #pragma unroll
            for (int i = 0; i < 4; i++) {
                int row = lrow + i * 32;
                bufA[i] = *(const uint4*)&Ea[(size_t)(s0 + row) * T_ + kb + lc8];
                bufB[i] = *(const uint4*)&Va[(size_t)(c0 + row) * T_ + kb + lc8];
            }
        }
        #pragma unroll
        for (int ks_i = 0; ks_i < 4; ks_i++) {
            const uint32_t koff = ks_i * 32;   // 16 bf16 = 32 bytes
            uint32_t a[2][4];
            #pragma unroll
            for (int mi = 0; mi < 2; mi++)
                ldsm4(a[mi][0], a[mi][1], a[mi][2], a[mi][3], aAddr[mi] + koff);
            #pragma unroll
            for (int p = 0; p < 4; p++) {
                uint32_t b0, b1, b2, b3;
                ldsm4(b0, b1, b2, b3, bAddr[p] + koff);
                #pragma unroll
                for (int mi = 0; mi < 2; mi++) {
                    mma_bf16(acc[mi][2 * p],     a[mi][0], a[mi][1], a[mi][2], a[mi][3], b0, b1);
                    mma_bf16(acc[mi][2 * p + 1], a[mi][0], a[mi][1], a[mi][2], a[mi][3], b2, b3);
                }
            }
        }
        __syncthreads();
        if (kt < KT - 1) {
            #pragma unroll
            for (int i = 0; i < 4; i++) {
                int row = lrow + i * 32;
                *(uint4*)&sm.A [row][lc8] = bufA[i];
                *(uint4*)&sm.Bv[row][lc8] = bufB[i];
            }
            __syncthreads();
        }
    }

    #pragma unroll
    for (int mi = 0; mi < 2; mi++) {
        int s = s0 + wm * 32 + mi * 16 + g;
        size_t base0 = ((size_t)bz * T_ + s) * C_;
        size_t base1 = ((size_t)bz * T_ + s + 8) * C_;
        #pragma unroll
        for (int ni = 0; ni < 8; ni++) {
            int c = c0 + wn * 64 + ni * 8 + tig * 2;
            float2 x0 = *(const float2*)&x[base0 + c];
            float2 x1 = *(const float2*)&x[base1 + c];
            *(float2*)&out[base0 + c] = make_float2(x0.x + acc[mi][ni][0], x0.y + acc[mi][ni][1]);
            *(float2*)&out[base1 + c] = make_float2(x1.x + acc[mi][ni][2], x1.y + acc[mi][ni][3]);
        }
    }
}

// ================================ launch =====================================
extern "C" void kernel_launch(void* const* d_in, const int* in_sizes, int n_in,
                              void* d_out, int out_size) {
    const float* x     = (const float*)d_in[0];
    const float* gamma = (const float*)d_in[1];
    const float* beta  = (const float*)d_in[2];
    const float* Wq    = (const float*)d_in[3];
    const float* bq    = (const float*)d_in[4];
    const float* Wk    = (const float*)d_in[5];
    const float* bk    = (const float*)d_in[6];
    const float* Wv    = (const float*)d_in[7];
    const float* bv    = (const float*)d_in[8];
    float* out = (float*)d_out;

    ln_kernel<<<NTOK, 256>>>(x, gamma, beta);
    qkv_kernel<<<dim3(NTOK / 128, C_ / 128, 3), 256>>>(Wq, bq, Wk, bk, Wv, bv);
    scores_kernel<<<dim3(T_ / 128, T_ / 128, B_), 256>>>();
    reduce_z_kernel<<<NTOK / 256, 256>>>();
    zv_kernel<<<dim3(T_ / 128, C_ / 128, B_), 256>>>();
    av_kernel<<<dim3(T_ / 128, C_ / 128, B_), 256>>>(x, out);
}

// round 5
// speedup vs baseline: 4.2576x; 1.0484x over previous
#include <cuda_runtime.h>
#include <cuda_bf16.h>
#include <cstdint>

#define B_   4
#define T_   4096
#define C_   256
#define NTOK (B_ * T_)   // 16384

// ---------------- scratch (static device arrays; no allocation) --------------
__device__ float g_gn[NTOK * C_];
__device__ float g_q [NTOK * C_];
__device__ float g_k [NTOK * C_];
__device__ float g_v [NTOK * C_];
__device__ __nv_bfloat16 g_e [(size_t)B_ * T_ * T_];   // E^T: [b][s][t], bf16
__device__ __nv_bfloat16 g_vt[(size_t)B_ * C_ * T_];   // V'^T: [b][c][t], bf16
__device__ float g_zpart[NTOK * 32];                   // per (b,t): 32 s-tile partials

// ---------------- helpers ------------------------------------------------------
__device__ __forceinline__ uint32_t smem_u32(const void* p) {
    uint32_t a;
    asm("{ .reg .u64 t; cvta.to.shared.u64 t, %1; cvt.u32.u64 %0, t; }" : "=r"(a) : "l"(p));
    return a;
}
__device__ __forceinline__ void cp16(uint32_t dst, const void* src) {
    asm volatile("cp.async.cg.shared.global [%0], [%1], 16;" :: "r"(dst), "l"(src));
}
__device__ __forceinline__ void cp_commit() {
    asm volatile("cp.async.commit_group;" ::: "memory");
}
template <int N> __device__ __forceinline__ void cp_wait() {
    asm volatile("cp.async.wait_group %0;" :: "n"(N) : "memory");
}
__device__ __forceinline__ void mma_tf32(float c[4],
                                         uint32_t a0, uint32_t a1, uint32_t a2, uint32_t a3,
                                         uint32_t b0, uint32_t b1) {
    asm volatile(
        "mma.sync.aligned.m16n8k8.row.col.f32.tf32.tf32.f32 "
        "{%0,%1,%2,%3}, {%4,%5,%6,%7}, {%8,%9}, {%0,%1,%2,%3};"
        : "+f"(c[0]), "+f"(c[1]), "+f"(c[2]), "+f"(c[3])
        : "r"(a0), "r"(a1), "r"(a2), "r"(a3), "r"(b0), "r"(b1));
}
__device__ __forceinline__ void mma_bf16(float c[4],
                                         uint32_t a0, uint32_t a1, uint32_t a2, uint32_t a3,
                                         uint32_t b0, uint32_t b1) {
    asm volatile(
        "mma.sync.aligned.m16n8k16.row.col.f32.bf16.bf16.f32 "
        "{%0,%1,%2,%3}, {%4,%5,%6,%7}, {%8,%9}, {%0,%1,%2,%3};"
        : "+f"(c[0]), "+f"(c[1]), "+f"(c[2]), "+f"(c[3])
        : "r"(a0), "r"(a1), "r"(a2), "r"(a3), "r"(b0), "r"(b1));
}
__device__ __forceinline__ void ldsm4(uint32_t& r0, uint32_t& r1, uint32_t& r2, uint32_t& r3,
                                      uint32_t addr) {
    asm volatile("ldmatrix.sync.aligned.m8n8.x4.shared.b16 {%0,%1,%2,%3}, [%4];"
                 : "=r"(r0), "=r"(r1), "=r"(r2), "=r"(r3) : "r"(addr));
}

// dyn smem layout (tf32 & bf16 GEMMs use identical byte sizes):
//   A0 @ 0       (18432 B)   B0 @ 18432
//   A1 @ 36864               B1 @ 55296      total 73728 B
#define STAGE_OFF 36864u
#define BOFF      18432u
#define DSMEM_SZ  73728

// =============================== LayerNorm ==================================
__global__ void __launch_bounds__(256) ln_kernel(const float* __restrict__ x,
                                                 const float* __restrict__ gamma,
                                                 const float* __restrict__ beta) {
    int t = blockIdx.x;
    int c = threadIdx.x;
    size_t idx = (size_t)t * C_ + c;
    float v = x[idx];
    float s = v, sq = v * v;
    #pragma unroll
    for (int o = 16; o > 0; o >>= 1) {
        s  += __shfl_xor_sync(0xffffffffu, s,  o);
        sq += __shfl_xor_sync(0xffffffffu, sq, o);
    }
    __shared__ float sh_s[8], sh_sq[8], sh_stats[2];
    int warp = c >> 5, lane = c & 31;
    if (lane == 0) { sh_s[warp] = s; sh_sq[warp] = sq; }
    __syncthreads();
    if (warp == 0) {
        float a = (lane < 8) ? sh_s[lane]  : 0.f;
        float b = (lane < 8) ? sh_sq[lane] : 0.f;
        #pragma unroll
        for (int o = 4; o > 0; o >>= 1) {
            a += __shfl_xor_sync(0xffffffffu, a, o);
            b += __shfl_xor_sync(0xffffffffu, b, o);
        }
        if (lane == 0) {
            float mu  = a * (1.f / C_);
            float var = b * (1.f / C_) - mu * mu;
            sh_stats[0] = mu;
            sh_stats[1] = rsqrtf(var + 1e-5f);
        }
    }
    __syncthreads();
    g_gn[idx] = (v - sh_stats[0]) * sh_stats[1] * gamma[c] + beta[c];
}

// ======== tf32 core (cp.async 2-stage): 128x128 tile, K=256, BK=32 ===========
// smem tiles: [128 rows][36 floats] (144B row stride, 16B-aligned chunks)
__device__ __forceinline__ void core_tf32_ca(char* dsm,
                                             const float* __restrict__ A,
                                             const float* __restrict__ Bm,
                                             int m0, int n0,
                                             float acc[2][8][4]) {
    const int tid  = threadIdx.x;
    const int lane = tid & 31;
    const int wid  = tid >> 5;
    const int wm   = wid >> 1;
    const int wn   = wid & 1;

    #pragma unroll
    for (int mi = 0; mi < 2; mi++)
        #pragma unroll
        for (int ni = 0; ni < 8; ni++)
            #pragma unroll
            for (int r = 0; r < 4; r++) acc[mi][ni][r] = 0.f;

    const uint32_t sA = smem_u32(dsm);
    const uint32_t sB = sA + BOFF;

    // ldmatrix fragment addresses (stage 0)
    const int arow = (lane & 7) + (lane & 8);
    const int acol = (lane & 16) ? 4 : 0;
    uint32_t aAddr[2];
    #pragma unroll
    for (int mi = 0; mi < 2; mi++)
        aAddr[mi] = sA + (uint32_t)(((wm * 32 + mi * 16 + arow) * 36 + acol) * 4);
    const int brow = (lane & 7) + ((lane & 16) ? 8 : 0);
    const int bcol = (lane & 8) ? 4 : 0;
    uint32_t bAddr[4];
    #pragma unroll
    for (int p = 0; p < 4; p++)
        bAddr[p] = sB + (uint32_t)(((wn * 64 + p * 16 + brow) * 36 + bcol) * 4);

    const int lrow = tid >> 3;          // 0..31
    const int lc4  = (tid & 7) * 4;     // 0..28

    // prologue: stage 0 loads
    #pragma unroll
    for (int i = 0; i < 4; i++) {
        int row = lrow + i * 32;
        uint32_t d = (uint32_t)((row * 36 + lc4) * 4);
        cp16(sA + d, &A [(size_t)(m0 + row) * 256 + lc4]);
        cp16(sB + d, &Bm[(size_t)(n0 + row) * 256 + lc4]);
    }
    cp_commit();

    for (int kt = 0; kt < 8; kt++) {
        if (kt < 7) {
            int kb = (kt + 1) * 32;
            uint32_t so = ((kt + 1) & 1) * STAGE_OFF;
            #pragma unroll
            for (int i = 0; i < 4; i++) {
                int row = lrow + i * 32;
                uint32_t d = so + (uint32_t)((row * 36 + lc4) * 4);
                cp16(sA + d, &A [(size_t)(m0 + row) * 256 + kb + lc4]);
                cp16(sB + d, &Bm[(size_t)(n0 + row) * 256 + kb + lc4]);
            }
            cp_commit();
            cp_wait<1>();
        } else {
            cp_wait<0>();
        }
        __syncthreads();

        const uint32_t so = (kt & 1) * STAGE_OFF;
        #pragma unroll
        for (int ks_i = 0; ks_i < 4; ks_i++) {
            const uint32_t koff = so + ks_i * 32;   // 8 f32 = 32 B
            uint32_t a[2][4];
            #pragma unroll
            for (int mi = 0; mi < 2; mi++)
                ldsm4(a[mi][0], a[mi][1], a[mi][2], a[mi][3], aAddr[mi] + koff);
            #pragma unroll
            for (int p = 0; p < 4; p++) {
                uint32_t b0, b1, b2, b3;
                ldsm4(b0, b1, b2, b3, bAddr[p] + koff);
                #pragma unroll
                for (int mi = 0; mi < 2; mi++) {
                    mma_tf32(acc[mi][2 * p],     a[mi][0], a[mi][1], a[mi][2], a[mi][3], b0, b1);
                    mma_tf32(acc[mi][2 * p + 1], a[mi][0], a[mi][1], a[mi][2], a[mi][3], b2, b3);
                }
            }
        }
        __syncthreads();
    }
}

// =============================== QKV ==========================================
__global__ void __launch_bounds__(256) qkv_kernel(const float* __restrict__ Wq,
                                                  const float* __restrict__ bq,
                                                  const float* __restrict__ Wk,
                                                  const float* __restrict__ bk,
                                                  const float* __restrict__ Wv,
                                                  const float* __restrict__ bv) {
    extern __shared__ char dsm[];
    const float* W; const float* bias; float* out;
    if (blockIdx.z == 0)      { W = Wq; bias = bq; out = g_q; }
    else if (blockIdx.z == 1) { W = Wk; bias = bk; out = g_k; }
    else                      { W = Wv; bias = bv; out = g_v; }

    float acc[2][8][4];
    core_tf32_ca(dsm, g_gn, W, blockIdx.x * 128, blockIdx.y * 128, acc);

    const int lane = threadIdx.x & 31, wid = threadIdx.x >> 5;
    const int wm = wid >> 1, wn = wid & 1, g = lane >> 2, tig = lane & 3;
    const int m0 = blockIdx.x * 128, n0 = blockIdx.y * 128;
    #pragma unroll
    for (int mi = 0; mi < 2; mi++) {
        int row = m0 + wm * 32 + mi * 16 + g;
        #pragma unroll
        for (int ni = 0; ni < 8; ni++) {
            int col = n0 + wn * 64 + ni * 8 + tig * 2;
            float bx = bias[col], by = bias[col + 1];
            *(float2*)&out[(size_t)row * 256 + col] =
                make_float2(acc[mi][ni][0] + bx, acc[mi][ni][1] + by);
            *(float2*)&out[(size_t)(row + 8) * 256 + col] =
                make_float2(acc[mi][ni][2] + bx, acc[mi][ni][3] + by);
        }
    }
}

// ====================== scores + exp + rowsum + E^T (bf16) ====================
__global__ void __launch_bounds__(256) scores_kernel() {
    extern __shared__ char dsm[];
    __shared__ float rs[128];

    const int bz = blockIdx.z;
    const int t0 = blockIdx.x * 128;   // m: query rows (softmax rows)
    const int s0 = blockIdx.y * 128;   // n: key cols
    const float* Q = g_q + (size_t)bz * T_ * C_;
    const float* K = g_k + (size_t)bz * T_ * C_;

    const int tid = threadIdx.x;
    if (tid < 128) rs[tid] = 0.f;

    float acc[2][8][4];
    core_tf32_ca(dsm, Q, K, t0, s0, acc);

    const int lane = tid & 31, wid = tid >> 5;
    const int wm = wid >> 1, wn = wid & 1, g = lane >> 2, tig = lane & 3;

    // exp(score / 16)
    #pragma unroll
    for (int mi = 0; mi < 2; mi++)
        #pragma unroll
        for (int ni = 0; ni < 8; ni++)
            #pragma unroll
            for (int r = 0; r < 4; r++)
                acc[mi][ni][r] = __expf(acc[mi][ni][r] * 0.0625f);

    // per-row partial sums over this block's 128 s-columns
    #pragma unroll
    for (int mi = 0; mi < 2; mi++) {
        float s0v = 0.f, s1v = 0.f;
        #pragma unroll
        for (int ni = 0; ni < 8; ni++) {
            s0v += acc[mi][ni][0] + acc[mi][ni][1];
            s1v += acc[mi][ni][2] + acc[mi][ni][3];
        }
        s0v += __shfl_xor_sync(0xffffffffu, s0v, 1);
        s0v += __shfl_xor_sync(0xffffffffu, s0v, 2);
        s1v += __shfl_xor_sync(0xffffffffu, s1v, 1);
        s1v += __shfl_xor_sync(0xffffffffu, s1v, 2);
        if (tig == 0) {
            atomicAdd(&rs[wm * 32 + mi * 16 + g],     s0v);
            atomicAdd(&rs[wm * 32 + mi * 16 + g + 8], s1v);
        }
    }
    __syncthreads();
    if (tid < 128)
        g_zpart[(size_t)(bz * T_ + t0 + tid) * 32 + blockIdx.y] = rs[tid];

    // stage transposed bf16 tile in dsm: et[s_local][t_local], [128][136]
    unsigned short* et = (unsigned short*)dsm;
    #pragma unroll
    for (int mi = 0; mi < 2; mi++) {
        int r0 = wm * 32 + mi * 16 + g;
        #pragma unroll
        for (int ni = 0; ni < 8; ni++) {
            int col = wn * 64 + ni * 8 + tig * 2;
            et[(size_t)col * 136 + r0]           = __bfloat16_as_ushort(__float2bfloat16(acc[mi][ni][0]));
            et[(size_t)(col + 1) * 136 + r0]     = __bfloat16_as_ushort(__float2bfloat16(acc[mi][ni][1]));
            et[(size_t)col * 136 + r0 + 8]       = __bfloat16_as_ushort(__float2bfloat16(acc[mi][ni][2]));
            et[(size_t)(col + 1) * 136 + r0 + 8] = __bfloat16_as_ushort(__float2bfloat16(acc[mi][ni][3]));
        }
    }
    __syncthreads();

    // coalesced store E^T[b][s0+sl][t0 .. t0+127]
    #pragma unroll
    for (int i = 0; i < 8; i++) {
        int lin = tid + i * 256;
        int sl = lin >> 4, c8 = (lin & 15) * 8;
        uint4 d = *(uint4*)&et[(size_t)sl * 136 + c8];
        *(uint4*)&g_e[(size_t)(bz * T_ + s0 + sl) * T_ + t0 + c8] = d;
    }
}

// ===== zv: zinv (merged reduce) + V'^T[c][t] = bf16(V[t][c]/Z_t) ==============
__global__ void __launch_bounds__(256) zv_kernel() {
    __shared__ unsigned short vs[128][136];
    __shared__ float zs[128];
    const int bz = blockIdx.z;
    const int t0 = blockIdx.x * 128;
    const int c0 = blockIdx.y * 128;
    const float* V = g_v + (size_t)bz * T_ * C_;
    const int tid = threadIdx.x;

    if (tid < 128) {
        float s = 0.f;
        #pragma unroll
        for (int j = 0; j < 32; j++) s += g_zpart[(size_t)(bz * T_ + t0 + tid) * 32 + j];
        zs[tid] = 1.f / s;
    }
    __syncthreads();

    #pragma unroll
    for (int i = 0; i < 8; i++) {
        int lin = tid + i * 256;
        int tl = lin >> 4, c8 = (lin & 15) * 8;
        float zi = zs[tl];
        float4 v0 = *(const float4*)&V[(size_t)(t0 + tl) * C_ + c0 + c8];
        float4 v1 = *(const float4*)&V[(size_t)(t0 + tl) * C_ + c0 + c8 + 4];
        vs[c8 + 0][tl] = __bfloat16_as_ushort(__float2bfloat16(v0.x * zi));
        vs[c8 + 1][tl] = __bfloat16_as_ushort(__float2bfloat16(v0.y * zi));
        vs[c8 + 2][tl] = __bfloat16_as_ushort(__float2bfloat16(v0.z * zi));
        vs[c8 + 3][tl] = __bfloat16_as_ushort(__float2bfloat16(v0.w * zi));
        vs[c8 + 4][tl] = __bfloat16_as_ushort(__float2bfloat16(v1.x * zi));
        vs[c8 + 5][tl] = __bfloat16_as_ushort(__float2bfloat16(v1.y * zi));
        vs[c8 + 6][tl] = __bfloat16_as_ushort(__float2bfloat16(v1.z * zi));
        vs[c8 + 7][tl] = __bfloat16_as_ushort(__float2bfloat16(v1.w * zi));
    }
    __syncthreads();
    #pragma unroll
    for (int i = 0; i < 8; i++) {
        int lin = tid + i * 256;
        int cl = lin >> 4, t8 = (lin & 15) * 8;
        uint4 d = *(uint4*)&vs[cl][t8];
        *(uint4*)&g_vt[(size_t)(bz * C_ + c0 + cl) * T_ + t0 + t8] = d;
    }
}

// ======= AV (bf16, cp.async): out[b,s,c] = x + sum_t E^T[s,t]*V'^T[c,t] ======
// smem tiles: [128 rows][72 bf16] (144B row stride)
__global__ void __launch_bounds__(256) av_kernel(const float* __restrict__ x,
                                                 float* __restrict__ out) {
    extern __shared__ char dsm[];
    const int bz = blockIdx.z;
    const int s0 = blockIdx.x * 128;
    const int c0 = blockIdx.y * 128;
    const __nv_bfloat16* Ea = g_e  + (size_t)bz * T_ * T_;
    const __nv_bfloat16* Va = g_vt + (size_t)bz * C_ * T_;

    const int tid = threadIdx.x;
    const int lane = tid & 31, wid = tid >> 5;
    const int wm = wid >> 1, wn = wid & 1, g = lane >> 2, tig = lane & 3;

    float acc[2][8][4];
    #pragma unroll
    for (int mi = 0; mi < 2; mi++)
        #pragma unroll
        for (int ni = 0; ni < 8; ni++)
            #pragma unroll
            for (int r = 0; r < 4; r++) acc[mi][ni][r] = 0.f;

    const uint32_t sA = smem_u32(dsm);
    const uint32_t sB = sA + BOFF;

    const int arow = (lane & 7) + (lane & 8);
    const int acol = (lane & 16) ? 8 : 0;    // bf16 cols
    uint32_t aAddr[2];
    #pragma unroll
    for (int mi = 0; mi < 2; mi++)
        aAddr[mi] = sA + (uint32_t)(((wm * 32 + mi * 16 + arow) * 72 + acol) * 2);
    const int brow = (lane & 7) + ((lane & 16) ? 8 : 0);
    const int bcol = (lane & 8) ? 8 : 0;
    uint32_t bAddr[4];
    #pragma unroll
    for (int p = 0; p < 4; p++)
        bAddr[p] = sB + (uint32_t)(((wn * 64 + p * 16 + brow) * 72 + bcol) * 2);

    const int lrow = tid >> 3;          // 0..31
    const int lc8  = (tid & 7) * 8;     // 0..56 (16B chunks)

    #pragma unroll
    for (int i = 0; i < 4; i++) {
        int row = lrow + i * 32;
        uint32_t d = (uint32_t)((row * 72 + lc8) * 2);
        cp16(sA + d, &Ea[(size_t)(s0 + row) * T_ + lc8]);
        cp16(sB + d, &Va[(size_t)(c0 + row) * T_ + lc8]);
    }
    cp_commit();

    const int KT = T_ / 64;   // 64 chunks of 64 bf16
    for (int kt = 0; kt < KT; kt++) {
        if (kt < KT - 1) {
            int kb = (kt + 1) * 64;
            uint32_t so = ((kt + 1) & 1) * STAGE_OFF;
            #pragma unroll
            for (int i = 0; i < 4; i++) {
                int row = lrow + i * 32;
                uint32_t d = so + (uint32_t)((row * 72 + lc8) * 2);
                cp16(sA + d, &Ea[(size_t)(s0 + row) * T_ + kb + lc8]);
                cp16(sB + d, &Va[(size_t)(c0 + row) * T_ + kb + lc8]);
            }
            cp_commit();
            cp_wait<1>();
        } else {
            cp_wait<0>();
        }
        __syncthreads();

        const uint32_t so = (kt & 1) * STAGE_OFF;
        #pragma unroll
        for (int ks_i = 0; ks_i < 4; ks_i++) {
            const uint32_t koff = so + ks_i * 32;   // 16 bf16 = 32 B
            uint32_t a[2][4];
            #pragma unroll
            for (int mi = 0; mi < 2; mi++)
                ldsm4(a[mi][0], a[mi][1], a[mi][2], a[mi][3], aAddr[mi] + koff);
            #pragma unroll
            for (int p = 0; p < 4; p++) {
                uint32_t b0, b1, b2, b3;
                ldsm4(b0, b1, b2, b3, bAddr[p] + koff);
                #pragma unroll
                for (int mi = 0; mi < 2; mi++) {
                    mma_bf16(acc[mi][2 * p],     a[mi][0], a[mi][1], a[mi][2], a[mi][3], b0, b1);
                    mma_bf16(acc[mi][2 * p + 1], a[mi][0], a[mi][1], a[mi][2], a[mi][3], b2, b3);
                }
            }
        }
        __syncthreads();
    }

    #pragma unroll
    for (int mi = 0; mi < 2; mi++) {
        int s = s0 + wm * 32 + mi * 16 + g;
        size_t base0 = ((size_t)bz * T_ + s) * C_;
        size_t base1 = ((size_t)bz * T_ + s + 8) * C_;
        #pragma unroll
        for (int ni = 0; ni < 8; ni++) {
            int c = c0 + wn * 64 + ni * 8 + tig * 2;
            float2 x0 = *(const float2*)&x[base0 + c];
            float2 x1 = *(const float2*)&x[base1 + c];
            *(float2*)&out[base0 + c] = make_float2(x0.x + acc[mi][ni][0], x0.y + acc[mi][ni][1]);
            *(float2*)&out[base1 + c] = make_float2(x1.x + acc[mi][ni][2], x1.y + acc[mi][ni][3]);
        }
    }
}

// ================================ launch =====================================
extern "C" void kernel_launch(void* const* d_in, const int* in_sizes, int n_in,
                              void* d_out, int out_size) {
    const float* x     = (const float*)d_in[0];
    const float* gamma = (const float*)d_in[1];
    const float* beta  = (const float*)d_in[2];
    const float* Wq    = (const float*)d_in[3];
    const float* bq    = (const float*)d_in[4];
    const float* Wk    = (const float*)d_in[5];
    const float* bk    = (const float*)d_in[6];
    const float* Wv    = (const float*)d_in[7];
    const float* bv    = (const float*)d_in[8];
    float* out = (float*)d_out;

    cudaFuncSetAttribute(qkv_kernel,    cudaFuncAttributeMaxDynamicSharedMemorySize, DSMEM_SZ);
    cudaFuncSetAttribute(scores_kernel, cudaFuncAttributeMaxDynamicSharedMemorySize, DSMEM_SZ);
    cudaFuncSetAttribute(av_kernel,     cudaFuncAttributeMaxDynamicSharedMemorySize, DSMEM_SZ);

    ln_kernel<<<NTOK, 256>>>(x, gamma, beta);
    qkv_kernel<<<dim3(NTOK / 128, C_ / 128, 3), 256, DSMEM_SZ>>>(Wq, bq, Wk, bk, Wv, bv);
    scores_kernel<<<dim3(T_ / 128, T_ / 128, B_), 256, DSMEM_SZ>>>();
    zv_kernel<<<dim3(T_ / 128, C_ / 128, B_), 256>>>();
    av_kernel<<<dim3(T_ / 128, C_ / 128, B_), 256, DSMEM_SZ>>>(x, out);
}

// round 6
// speedup vs baseline: 5.7641x; 1.3538x over previous
#include <cuda_runtime.h>
#include <cuda_bf16.h>
#include <cstdint>

#define B_   4
#define T_   4096
#define C_   256
#define NTOK (B_ * T_)   // 16384

typedef __nv_bfloat16 bf16;

// ---------------- scratch (static device arrays; no allocation) --------------
__device__ bf16  g_gn[NTOK * C_];
__device__ bf16  g_wq[C_ * C_], g_wk[C_ * C_], g_wv[C_ * C_];
__device__ bf16  g_q [NTOK * C_];
__device__ bf16  g_k [NTOK * C_];
__device__ bf16  g_v [NTOK * C_];
__device__ bf16  g_e [(size_t)B_ * T_ * T_];   // E^T: [b][s][t]
__device__ bf16  g_vt[(size_t)B_ * C_ * T_];   // V'^T: [b][c][t]
__device__ float g_zpart[NTOK * 32];           // per (b,t): 32 s-tile partials

// ---------------- helpers ------------------------------------------------------
__device__ __forceinline__ uint32_t smem_u32(const void* p) {
    uint32_t a;
    asm("{ .reg .u64 t; cvta.to.shared.u64 t, %1; cvt.u32.u64 %0, t; }" : "=r"(a) : "l"(p));
    return a;
}
__device__ __forceinline__ void cp16(uint32_t dst, const void* src) {
    asm volatile("cp.async.cg.shared.global [%0], [%1], 16;" :: "r"(dst), "l"(src));
}
__device__ __forceinline__ void cp_commit() {
    asm volatile("cp.async.commit_group;" ::: "memory");
}
template <int N> __device__ __forceinline__ void cp_wait() {
    asm volatile("cp.async.wait_group %0;" :: "n"(N) : "memory");
}
__device__ __forceinline__ void mma_bf16(float c[4],
                                         uint32_t a0, uint32_t a1, uint32_t a2, uint32_t a3,
                                         uint32_t b0, uint32_t b1) {
    asm volatile(
        "mma.sync.aligned.m16n8k16.row.col.f32.bf16.bf16.f32 "
        "{%0,%1,%2,%3}, {%4,%5,%6,%7}, {%8,%9}, {%0,%1,%2,%3};"
        : "+f"(c[0]), "+f"(c[1]), "+f"(c[2]), "+f"(c[3])
        : "r"(a0), "r"(a1), "r"(a2), "r"(a3), "r"(b0), "r"(b1));
}
__device__ __forceinline__ void ldsm4(uint32_t& r0, uint32_t& r1, uint32_t& r2, uint32_t& r3,
                                      uint32_t addr) {
    asm volatile("ldmatrix.sync.aligned.m8n8.x4.shared.b16 {%0,%1,%2,%3}, [%4];"
                 : "=r"(r0), "=r"(r1), "=r"(r2), "=r"(r3) : "r"(addr));
}
__device__ __forceinline__ uint32_t pack_bf16(float a, float b) {
    uint32_t lo = __bfloat16_as_ushort(__float2bfloat16(a));
    uint32_t hi = __bfloat16_as_ushort(__float2bfloat16(b));
    return lo | (hi << 16);
}

// bf16 smem tiles: [rows][72 bf16] (144 B row stride)
// 128x128 core: A 128x64 @0 (18432 B), B 128x64 @18432; stage=36864, x2=73728
#define BOFF128   18432u
#define STG128    36864u
#define DSM128    73728
// av: A 128x64 @0 (18432), B 256x64 @18432 (36864); stage=55296, x2=110592
#define BOFF_AV   18432u
#define STG_AV    55296u
#define DSM_AV    110592

// =============================== LayerNorm (bf16 out) ========================
__global__ void __launch_bounds__(256) ln_kernel(const float* __restrict__ x,
                                                 const float* __restrict__ gamma,
                                                 const float* __restrict__ beta) {
    int t = blockIdx.x;
    int c = threadIdx.x;
    size_t idx = (size_t)t * C_ + c;
    float v = x[idx];
    float s = v, sq = v * v;
    #pragma unroll
    for (int o = 16; o > 0; o >>= 1) {
        s  += __shfl_xor_sync(0xffffffffu, s,  o);
        sq += __shfl_xor_sync(0xffffffffu, sq, o);
    }
    __shared__ float sh_s[8], sh_sq[8], sh_stats[2];
    int warp = c >> 5, lane = c & 31;
    if (lane == 0) { sh_s[warp] = s; sh_sq[warp] = sq; }
    __syncthreads();
    if (warp == 0) {
        float a = (lane < 8) ? sh_s[lane]  : 0.f;
        float b = (lane < 8) ? sh_sq[lane] : 0.f;
        #pragma unroll
        for (int o = 4; o > 0; o >>= 1) {
            a += __shfl_xor_sync(0xffffffffu, a, o);
            b += __shfl_xor_sync(0xffffffffu, b, o);
        }
        if (lane == 0) {
            float mu  = a * (1.f / C_);
            float var = b * (1.f / C_) - mu * mu;
            sh_stats[0] = mu;
            sh_stats[1] = rsqrtf(var + 1e-5f);
        }
    }
    __syncthreads();
    g_gn[idx] = __float2bfloat16((v - sh_stats[0]) * sh_stats[1] * gamma[c] + beta[c]);
}

// ======================= weight fp32 -> bf16 converter =======================
__global__ void __launch_bounds__(256) wconv_kernel(const float* __restrict__ Wq,
                                                    const float* __restrict__ Wk,
                                                    const float* __restrict__ Wv) {
    const float* src = (blockIdx.y == 0) ? Wq : (blockIdx.y == 1) ? Wk : Wv;
    bf16* dst = (blockIdx.y == 0) ? g_wq : (blockIdx.y == 1) ? g_wk : g_wv;
    int i = (blockIdx.x * 256 + threadIdx.x) * 4;
    float4 v = *(const float4*)&src[i];
    uint32_t p0 = pack_bf16(v.x, v.y);
    uint32_t p1 = pack_bf16(v.z, v.w);
    *(uint2*)&dst[i] = make_uint2(p0, p1);
}

// ===== bf16 core (cp.async 2-stage): 128x128 tile, K=256, 4 chunks of 64 =====
__device__ __forceinline__ void core_bf16_128(char* dsm,
                                              const bf16* __restrict__ A,
                                              const bf16* __restrict__ Bm,
                                              int m0, int n0,
                                              float acc[2][8][4]) {
    const int tid  = threadIdx.x;
    const int lane = tid & 31;
    const int wid  = tid >> 5;
    const int wm   = wid >> 1;
    const int wn   = wid & 1;

    #pragma unroll
    for (int mi = 0; mi < 2; mi++)
        #pragma unroll
        for (int ni = 0; ni < 8; ni++)
            #pragma unroll
            for (int r = 0; r < 4; r++) acc[mi][ni][r] = 0.f;

    const uint32_t sA = smem_u32(dsm);
    const uint32_t sB = sA + BOFF128;

    const int arow = (lane & 7) + (lane & 8);
    const int acol = (lane & 16) ? 8 : 0;
    uint32_t aAddr[2];
    #pragma unroll
    for (int mi = 0; mi < 2; mi++)
        aAddr[mi] = sA + (uint32_t)(((wm * 32 + mi * 16 + arow) * 72 + acol) * 2);
    const int brow = (lane & 7) + ((lane & 16) ? 8 : 0);
    const int bcol = (lane & 8) ? 8 : 0;
    uint32_t bAddr[4];
    #pragma unroll
    for (int p = 0; p < 4; p++)
        bAddr[p] = sB + (uint32_t)(((wn * 64 + p * 16 + brow) * 72 + bcol) * 2);

    const int lrow = tid >> 3;          // 0..31
    const int lc8  = (tid & 7) * 8;     // bf16 col, 16B chunks

    #pragma unroll
    for (int i = 0; i < 4; i++) {
        int row = lrow + i * 32;
        uint32_t d = (uint32_t)((row * 72 + lc8) * 2);
        cp16(sA + d, &A [(size_t)(m0 + row) * C_ + lc8]);
        cp16(sB + d, &Bm[(size_t)(n0 + row) * C_ + lc8]);
    }
    cp_commit();

    for (int kt = 0; kt < 4; kt++) {
        if (kt < 3) {
            int kb = (kt + 1) * 64;
            uint32_t so = ((kt + 1) & 1) * STG128;
            #pragma unroll
            for (int i = 0; i < 4; i++) {
                int row = lrow + i * 32;
                uint32_t d = so + (uint32_t)((row * 72 + lc8) * 2);
                cp16(sA + d, &A [(size_t)(m0 + row) * C_ + kb + lc8]);
                cp16(sB + d, &Bm[(size_t)(n0 + row) * C_ + kb + lc8]);
            }
            cp_commit();
            cp_wait<1>();
        } else {
            cp_wait<0>();
        }
        __syncthreads();

        const uint32_t so = (kt & 1) * STG128;
        #pragma unroll
        for (int ks_i = 0; ks_i < 4; ks_i++) {
            const uint32_t koff = so + ks_i * 32;   // 16 bf16 = 32 B
            uint32_t a[2][4];
            #pragma unroll
            for (int mi = 0; mi < 2; mi++)
                ldsm4(a[mi][0], a[mi][1], a[mi][2], a[mi][3], aAddr[mi] + koff);
            #pragma unroll
            for (int p = 0; p < 4; p++) {
                uint32_t b0, b1, b2, b3;
                ldsm4(b0, b1, b2, b3, bAddr[p] + koff);
                #pragma unroll
                for (int mi = 0; mi < 2; mi++) {
                    mma_bf16(acc[mi][2 * p],     a[mi][0], a[mi][1], a[mi][2], a[mi][3], b0, b1);
                    mma_bf16(acc[mi][2 * p + 1], a[mi][0], a[mi][1], a[mi][2], a[mi][3], b2, b3);
                }
            }
        }
        __syncthreads();
    }
}

// =============================== QKV (bf16) ===================================
__global__ void __launch_bounds__(256) qkv_kernel(const float* __restrict__ bq,
                                                  const float* __restrict__ bk,
                                                  const float* __restrict__ bv) {
    extern __shared__ char dsm[];
    const bf16* W; const float* bias; bf16* out;
    if (blockIdx.z == 0)      { W = g_wq; bias = bq; out = g_q; }
    else if (blockIdx.z == 1) { W = g_wk; bias = bk; out = g_k; }
    else                      { W = g_wv; bias = bv; out = g_v; }

    float acc[2][8][4];
    core_bf16_128(dsm, g_gn, W, blockIdx.x * 128, blockIdx.y * 128, acc);

    const int lane = threadIdx.x & 31, wid = threadIdx.x >> 5;
    const int wm = wid >> 1, wn = wid & 1, g = lane >> 2, tig = lane & 3;
    const int m0 = blockIdx.x * 128, n0 = blockIdx.y * 128;
    #pragma unroll
    for (int mi = 0; mi < 2; mi++) {
        int row = m0 + wm * 32 + mi * 16 + g;
        #pragma unroll
        for (int ni = 0; ni < 8; ni++) {
            int col = n0 + wn * 64 + ni * 8 + tig * 2;
            float bx = bias[col], by = bias[col + 1];
            *(uint32_t*)&out[(size_t)row * C_ + col] =
                pack_bf16(acc[mi][ni][0] + bx, acc[mi][ni][1] + by);
            *(uint32_t*)&out[(size_t)(row + 8) * C_ + col] =
                pack_bf16(acc[mi][ni][2] + bx, acc[mi][ni][3] + by);
        }
    }
}

// =============== scores (bf16) + exp + rowsum + E^T store =====================
__global__ void __launch_bounds__(256) scores_kernel() {
    extern __shared__ char dsm[];
    __shared__ float rs[128];

    const int bz = blockIdx.z;
    const int t0 = blockIdx.x * 128;   // query rows (softmax rows)
    const int s0 = blockIdx.y * 128;   // key cols
    const bf16* Q = g_q + (size_t)bz * T_ * C_;
    const bf16* K = g_k + (size_t)bz * T_ * C_;

    const int tid = threadIdx.x;
    if (tid < 128) rs[tid] = 0.f;

    float acc[2][8][4];
    core_bf16_128(dsm, Q, K, t0, s0, acc);

    const int lane = tid & 31, wid = tid >> 5;
    const int wm = wid >> 1, wn = wid & 1, g = lane >> 2, tig = lane & 3;

    #pragma unroll
    for (int mi = 0; mi < 2; mi++)
        #pragma unroll
        for (int ni = 0; ni < 8; ni++)
            #pragma unroll
            for (int r = 0; r < 4; r++)
                acc[mi][ni][r] = __expf(acc[mi][ni][r] * 0.0625f);

    #pragma unroll
    for (int mi = 0; mi < 2; mi++) {
        float s0v = 0.f, s1v = 0.f;
        #pragma unroll
        for (int ni = 0; ni < 8; ni++) {
            s0v += acc[mi][ni][0] + acc[mi][ni][1];
            s1v += acc[mi][ni][2] + acc[mi][ni][3];
        }
        s0v += __shfl_xor_sync(0xffffffffu, s0v, 1);
        s0v += __shfl_xor_sync(0xffffffffu, s0v, 2);
        s1v += __shfl_xor_sync(0xffffffffu, s1v, 1);
        s1v += __shfl_xor_sync(0xffffffffu, s1v, 2);
        if (tig == 0) {
            atomicAdd(&rs[wm * 32 + mi * 16 + g],     s0v);
            atomicAdd(&rs[wm * 32 + mi * 16 + g + 8], s1v);
        }
    }
    __syncthreads();
    if (tid < 128)
        g_zpart[(size_t)(bz * T_ + t0 + tid) * 32 + blockIdx.y] = rs[tid];

    // stage transposed bf16 tile in dsm: et[s_local][t_local], [128][136]
    unsigned short* et = (unsigned short*)dsm;
    #pragma unroll
    for (int mi = 0; mi < 2; mi++) {
        int r0 = wm * 32 + mi * 16 + g;
        #pragma unroll
        for (int ni = 0; ni < 8; ni++) {
            int col = wn * 64 + ni * 8 + tig * 2;
            et[(size_t)col * 136 + r0]           = __bfloat16_as_ushort(__float2bfloat16(acc[mi][ni][0]));
            et[(size_t)(col + 1) * 136 + r0]     = __bfloat16_as_ushort(__float2bfloat16(acc[mi][ni][1]));
            et[(size_t)col * 136 + r0 + 8]       = __bfloat16_as_ushort(__float2bfloat16(acc[mi][ni][2]));
            et[(size_t)(col + 1) * 136 + r0 + 8] = __bfloat16_as_ushort(__float2bfloat16(acc[mi][ni][3]));
        }
    }
    __syncthreads();
    #pragma unroll
    for (int i = 0; i < 8; i++) {
        int lin = tid + i * 256;
        int sl = lin >> 4, c8 = (lin & 15) * 8;
        uint4 d = *(uint4*)&et[(size_t)sl * 136 + c8];
        *(uint4*)&g_e[(size_t)(bz * T_ + s0 + sl) * T_ + t0 + c8] = d;
    }
}

// ===== zv: zinv + V'^T[c][t] = bf16(V[t][c]/Z_t) ==============================
__global__ void __launch_bounds__(256) zv_kernel() {
    __shared__ unsigned short vs[128][136];
    __shared__ float zs[128];
    const int bz = blockIdx.z;
    const int t0 = blockIdx.x * 128;
    const int c0 = blockIdx.y * 128;
    const bf16* V = g_v + (size_t)bz * T_ * C_;
    const int tid = threadIdx.x;

    if (tid < 128) {
        float s = 0.f;
        #pragma unroll
        for (int j = 0; j < 32; j++) s += g_zpart[(size_t)(bz * T_ + t0 + tid) * 32 + j];
        zs[tid] = 1.f / s;
    }
    __syncthreads();

    #pragma unroll
    for (int i = 0; i < 8; i++) {
        int lin = tid + i * 256;
        int tl = lin >> 4, c8 = (lin & 15) * 8;
        float zi = zs[tl];
        uint4 raw = *(const uint4*)&V[(size_t)(t0 + tl) * C_ + c0 + c8];
        const unsigned short* u = (const unsigned short*)&raw;
        #pragma unroll
        for (int j = 0; j < 8; j++) {
            float f = __bfloat162float(__ushort_as_bfloat16(u[j])) * zi;
            vs[c8 + j][tl] = __bfloat16_as_ushort(__float2bfloat16(f));
        }
    }
    __syncthreads();
    #pragma unroll
    for (int i = 0; i < 8; i++) {
        int lin = tid + i * 256;
        int cl = lin >> 4, t8 = (lin & 15) * 8;
        uint4 d = *(uint4*)&vs[cl][t8];
        *(uint4*)&g_vt[(size_t)(bz * C_ + c0 + cl) * T_ + t0 + t8] = d;
    }
}

// === AV (bf16, 512 thr, 128x256 tile): out = x + E^T · V'^T over K=4096 ======
__global__ void __launch_bounds__(512) av_kernel(const float* __restrict__ x,
                                                 float* __restrict__ out) {
    extern __shared__ char dsm[];
    const int bz = blockIdx.y;
    const int s0 = blockIdx.x * 128;
    const bf16* Ea = g_e  + (size_t)bz * T_ * T_;
    const bf16* Va = g_vt + (size_t)bz * C_ * T_;

    const int tid = threadIdx.x;
    const int lane = tid & 31, wid = tid >> 5;
    const int wm = wid >> 2, wn = wid & 3;      // 4x4 warp grid, 32x64 per warp
    const int g = lane >> 2, tig = lane & 3;

    float acc[2][8][4];
    #pragma unroll
    for (int mi = 0; mi < 2; mi++)
        #pragma unroll
        for (int ni = 0; ni < 8; ni++)
            #pragma unroll
            for (int r = 0; r < 4; r++) acc[mi][ni][r] = 0.f;

    const uint32_t sA = smem_u32(dsm);
    const uint32_t sB = sA + BOFF_AV;

    const int arow = (lane & 7) + (lane & 8);
    const int acol = (lane & 16) ? 8 : 0;
    uint32_t aAddr[2];
    #pragma unroll
    for (int mi = 0; mi < 2; mi++)
        aAddr[mi] = sA + (uint32_t)(((wm * 32 + mi * 16 + arow) * 72 + acol) * 2);
    const int brow = (lane & 7) + ((lane & 16) ? 8 : 0);
    const int bcol = (lane & 8) ? 8 : 0;
    uint32_t bAddr[4];
    #pragma unroll
    for (int p = 0; p < 4; p++)
        bAddr[p] = sB + (uint32_t)(((wn * 64 + p * 16 + brow) * 72 + bcol) * 2);

    const int lrow = tid >> 3;          // 0..63
    const int lc8  = (tid & 7) * 8;

    // prologue
    #pragma unroll
    for (int i = 0; i < 2; i++) {
        int row = lrow + i * 64;
        cp16(sA + (uint32_t)((row * 72 + lc8) * 2), &Ea[(size_t)(s0 + row) * T_ + lc8]);
    }
    #pragma unroll
    for (int i = 0; i < 4; i++) {
        int row = lrow + i * 64;
        cp16(sB + (uint32_t)((row * 72 + lc8) * 2), &Va[(size_t)row * T_ + lc8]);
    }
    cp_commit();

    const int KT = T_ / 64;   // 64
    for (int kt = 0; kt < KT; kt++) {
        if (kt < KT - 1) {
            int kb = (kt + 1) * 64;
            uint32_t so = ((kt + 1) & 1) * STG_AV;
            #pragma unroll
            for (int i = 0; i < 2; i++) {
                int row = lrow + i * 64;
                cp16(sA + so + (uint32_t)((row * 72 + lc8) * 2),
                     &Ea[(size_t)(s0 + row) * T_ + kb + lc8]);
            }
            #pragma unroll
            for (int i = 0; i < 4; i++) {
                int row = lrow + i * 64;
                cp16(sB + so + (uint32_t)((row * 72 + lc8) * 2),
                     &Va[(size_t)row * T_ + kb + lc8]);
            }
            cp_commit();
            cp_wait<1>();
        } else {
            cp_wait<0>();
        }
        __syncthreads();

        const uint32_t so = (kt & 1) * STG_AV;
        #pragma unroll
        for (int ks_i = 0; ks_i < 4; ks_i++) {
            const uint32_t koff = so + ks_i * 32;
            uint32_t a[2][4];
            #pragma unroll
            for (int mi = 0; mi < 2; mi++)
                ldsm4(a[mi][0], a[mi][1], a[mi][2], a[mi][3], aAddr[mi] + koff);
            #pragma unroll
            for (int p = 0; p < 4; p++) {
                uint32_t b0, b1, b2, b3;
                ldsm4(b0, b1, b2, b3, bAddr[p] + koff);
                #pragma unroll
                for (int mi = 0; mi < 2; mi++) {
                    mma_bf16(acc[mi][2 * p],     a[mi][0], a[mi][1], a[mi][2], a[mi][3], b0, b1);
                    mma_bf16(acc[mi][2 * p + 1], a[mi][0], a[mi][1], a[mi][2], a[mi][3], b2, b3);
                }
            }
        }
        __syncthreads();
    }

    #pragma unroll
    for (int mi = 0; mi < 2; mi++) {
        int s = s0 + wm * 32 + mi * 16 + g;
        size_t base0 = ((size_t)bz * T_ + s) * C_;
        size_t base1 = ((size_t)bz * T_ + s + 8) * C_;
        #pragma unroll
        for (int ni = 0; ni < 8; ni++) {
            int c = wn * 64 + ni * 8 + tig * 2;
            float2 x0 = *(const float2*)&x[base0 + c];
            float2 x1 = *(const float2*)&x[base1 + c];
            *(float2*)&out[base0 + c] = make_float2(x0.x + acc[mi][ni][0], x0.y + acc[mi][ni][1]);
            *(float2*)&out[base1 + c] = make_float2(x1.x + acc[mi][ni][2], x1.y + acc[mi][ni][3]);
        }
    }
}

// ================================ launch =====================================
extern "C" void kernel_launch(void* const* d_in, const int* in_sizes, int n_in,
                              void* d_out, int out_size) {
    const float* x     = (const float*)d_in[0];
    const float* gamma = (const float*)d_in[1];
    const float* beta  = (const float*)d_in[2];
    const float* Wq    = (const float*)d_in[3];
    const float* bq    = (const float*)d_in[4];
    const float* Wk    = (const float*)d_in[5];
    const float* bk    = (const float*)d_in[6];
    const float* Wv    = (const float*)d_in[7];
    const float* bv    = (const float*)d_in[8];
    float* out = (float*)d_out;

    cudaFuncSetAttribute(qkv_kernel,    cudaFuncAttributeMaxDynamicSharedMemorySize, DSM128);
    cudaFuncSetAttribute(scores_kernel, cudaFuncAttributeMaxDynamicSharedMemorySize, DSM128);
    cudaFuncSetAttribute(av_kernel,     cudaFuncAttributeMaxDynamicSharedMemorySize, DSM_AV);

    ln_kernel<<<NTOK, 256>>>(x, gamma, beta);
    wconv_kernel<<<dim3(64, 3), 256>>>(Wq, Wk, Wv);
    qkv_kernel<<<dim3(NTOK / 128, C_ / 128, 3), 256, DSM128>>>(bq, bk, bv);
    scores_kernel<<<dim3(T_ / 128, T_ / 128, B_), 256, DSM128>>>();
    zv_kernel<<<dim3(T_ / 128, C_ / 128, B_), 256>>>();
    av_kernel<<<dim3(T_ / 128, B_), 512, DSM_AV>>>(x, out);
}